// round 15
// baseline (speedup 1.0000x reference)
#include <cuda_runtime.h>
#include <math.h>

#define D_DIM 131072
#define K_SEL 5
#define ELEMS 16                      // elements per thread (512 per warp)
#define WARPS_PER_ROW 256             // D_DIM / 512
#define TPB 256
#define MAX_B 128
#define NCAND (WARPS_PER_ROW * K_SEL) // 1280 candidates per row
#define CTAS_PER_B 32                 // 256 warps / 8 warps per CTA
#define ZBUF_BYTES 16384              // 16KB smem zero buffer
#define FILL_SLICE_BYTES (K_SEL * D_DIM * 4 / CTAS_PER_B)  // 81920
#define FILL_OPS (FILL_SLICE_BYTES / ZBUF_BYTES)           // 5

// inter-CTA scratch (no allocations allowed)
__device__ unsigned long long g_cand[MAX_B * NCAND];
__device__ int g_arrive[MAX_B];   // zero-initialized; self-resetting per replay

// monotonic float->uint transform (order-preserving incl. negatives)
__device__ __forceinline__ unsigned ford(float f) {
    unsigned u = __float_as_uint(f);
    return u ^ (((int)u >> 31) | 0x80000000u);
}

// element id e (0..15) -> global index within the row (monotonic in e)
__device__ __forceinline__ int eidx(int base, int lane, int e) {
    return base + ((lane + (e >> 2) * 32) << 2) + (e & 3);
}

__device__ __forceinline__ unsigned redux_max_u32(unsigned v) {
    unsigned r;
    asm("redux.sync.max.u32 %0, %1, 0xffffffff;" : "=r"(r) : "r"(v));
    return r;
}
__device__ __forceinline__ int redux_min_s32(int v) {
    int r;
    asm("redux.sync.min.s32 %0, %1, 0xffffffff;" : "=r"(r) : "r"(v));
    return r;
}

// ---------------------------------------------------------------------------
// Single fused kernel, READ-PHASE-FIRST ordering:
//   1. issue the 4 LDG.128 immediately (read burst)
//   2. zero smem staging buffer under load latency
//   3. slim warp top-5 (redux argmax + top-2 promote)
//   4. THEN issue the TMA zero-fill slice (write burst after reads)
//   5. drain, row ticket; last CTA merges + scatters
// ---------------------------------------------------------------------------
__global__ void __launch_bounds__(TPB, 3)
fused_topk_fill(const float* __restrict__ sims,
                float* __restrict__ out,
                int idx_off) {
    __shared__ float4 zbuf[ZBUF_BYTES / 16];
    __shared__ unsigned long long s_warp[8];
    __shared__ unsigned long long s_win;
    __shared__ int s_last;
    const int t = threadIdx.x;
    const int b_row = blockIdx.x / CTAS_PER_B;

    // ---- 1) issue reads FIRST: 4 back-to-back LDG.128 ----
    const int gw   = (blockIdx.x * TPB + t) >> 5;
    const int lane = t & 31;
    const int w    = gw % WARPS_PER_ROW;
    const int base = w * (ELEMS * 32);       // 512 elems per warp
    const float4* p = reinterpret_cast<const float4*>(
        sims + (size_t)b_row * D_DIM + base);
    float4 r[4];
#pragma unroll
    for (int i = 0; i < 4; i++) r[i] = p[lane + i * 32];

    // ---- 2) zero the smem staging buffer (overlaps load latency) ----
    const float4 z = make_float4(0.f, 0.f, 0.f, 0.f);
#pragma unroll
    for (int i = t; i < ZBUF_BYTES / 16; i += TPB) zbuf[i] = z;

    float c[ELEMS];
#pragma unroll
    for (int i = 0; i < 4; i++) {
        c[4*i+0] = r[i].x; c[4*i+1] = r[i].y;
        c[4*i+2] = r[i].z; c[4*i+3] = r[i].w;
    }

    // ---- 3) per-thread top-1 / top-2, then warp top-5 ----
    float bv = -INFINITY; int be = 0;
#pragma unroll
    for (int e = 0; e < ELEMS; e++)
        if (c[e] > bv) { bv = c[e]; be = e; }
    int bi = eidx(base, lane, be);

    float sv = -INFINITY; int se = 0;
#pragma unroll
    for (int e = 0; e < ELEMS; e++) {
        float val = (e == be) ? -INFINITY : c[e];
        if (val > sv) { sv = val; se = e; }
    }
    bool have2 = true;

    unsigned dead = 0u;
#pragma unroll
    for (int rr = 0; rr < K_SEL; rr++) {
        unsigned key  = ford(bv);
        unsigned wkey = redux_max_u32(key);
        int cand = (key == wkey) ? bi : 0x7fffffff;
        int wi   = redux_min_s32(cand);

        if (lane == rr)
            g_cand[(b_row * WARPS_PER_ROW + w) * K_SEL + rr] =
                ((unsigned long long)wkey << 32) | (unsigned)(~wi);

        if (bi == wi) {                   // exactly one lane owns the winner
            dead |= (1u << be);
            if (have2) {                  // cheap promote (typical path)
                bv = sv; be = se; bi = eidx(base, lane, se);
                have2 = false;
            } else {                      // rare: same thread consumed twice+
                bv = -INFINITY; be = 0;
#pragma unroll
                for (int e = 0; e < ELEMS; e++) {
                    float val = ((dead >> e) & 1u) ? -INFINITY : c[e];
                    if (val > bv) { bv = val; be = e; }
                }
                bi = eidx(base, lane, be);
            }
        }
    }

    // ---- 4) NOW issue the write burst: FILL_OPS x 16KB bulk stores ----
    __syncthreads();                      // zbuf fully zeroed by all threads
    asm volatile("fence.proxy.async.shared::cta;" ::: "memory");
    char* dst = (char*)(out + idx_off) +
                (long long)blockIdx.x * FILL_SLICE_BYTES;
    if (t < FILL_OPS) {
        unsigned saddr = (unsigned)__cvta_generic_to_shared(zbuf);
        asm volatile(
            "cp.async.bulk.global.shared::cta.bulk_group [%0], [%1], %2;"
            :: "l"(dst + t * ZBUF_BYTES), "r"(saddr), "r"(ZBUF_BYTES)
            : "memory");
        asm volatile("cp.async.bulk.commit_group;" ::: "memory");
        asm volatile("cp.async.bulk.wait_group 0;" ::: "memory");
    }

    // ---- 5) publish + row ticket ----
    __syncthreads();
    __threadfence();                      // publish g_cand + fill completion
    if (t == 0)
        s_last = (atomicAdd(&g_arrive[b_row], 1) == CTAS_PER_B - 1);
    __syncthreads();
    if (!s_last) return;

    // =============== last CTA of this row: merge + scatter ===============
    __threadfence();                      // acquire other CTAs' writes

    unsigned long long k[5];
#pragma unroll
    for (int s = 0; s < 5; s++)
        k[s] = g_cand[b_row * NCAND + t + s * 256];

    const int wid = t >> 5;
    const int lane2 = t & 31;
#pragma unroll
    for (int rr = 0; rr < K_SEL; rr++) {
        unsigned long long m = k[0];
#pragma unroll
        for (int s = 1; s < 5; s++) if (k[s] > m) m = k[s];
#pragma unroll
        for (int off = 16; off >= 1; off >>= 1) {
            unsigned long long o = __shfl_down_sync(0xffffffffu, m, off);
            if (o > m) m = o;
        }
        if (lane2 == 0) s_warp[wid] = m;
        __syncthreads();
        if (t < 32) {
            unsigned long long f = (lane2 < 8) ? s_warp[lane2] : 0ull;
#pragma unroll
            for (int off = 4; off >= 1; off >>= 1) {
                unsigned long long o = __shfl_down_sync(0xffffffffu, f, off);
                if (o > f) f = o;
            }
            if (lane2 == 0) s_win = f;
        }
        __syncthreads();
        unsigned long long win = s_win;
#pragma unroll
        for (int s = 0; s < 5; s++) if (k[s] == win) k[s] = 0ull;
        if (t == 0) {
            int idx = (int)(~(unsigned)win);
            if (idx_off > 0) out[b_row * K_SEL + rr] = (float)idx;
            out[(size_t)idx_off + ((size_t)b_row * K_SEL + rr) * D_DIM + idx]
                = 1.0f;
        }
        __syncthreads();
    }

    if (t == 0) g_arrive[b_row] = 0;      // reset for next graph replay
}

extern "C" void kernel_launch(void* const* d_in, const int* in_sizes, int n_in,
                              void* d_out, int out_size) {
    const float* sims = (const float*)d_in[0];
    int B = in_sizes[0] / D_DIM;
    if (B < 1) B = 1;
    if (B > MAX_B) B = MAX_B;

    long long soft = (long long)B * K_SEL * D_DIM;
    long long idx_off_ll = (long long)out_size - soft;
    int idx_off = (idx_off_ll > 0) ? (int)idx_off_ll : 0;

    fused_topk_fill<<<B * CTAS_PER_B, TPB>>>(sims, (float*)d_out, idx_off);
}